// round 14
// baseline (speedup 1.0000x reference)
#include <cuda_runtime.h>
#include <cuda_bf16.h>
#include <cstdint>

#define N_NODES 20000
#define BATCH 512
#define EMBED_DIM 32
#define NUM_SAMPLES 5001
#define TD_MAX 5000.0f

#define N4 5000                    // float4 columns per row
#define XTILES 20
#define BG 8                       // batch rows per lambda block
#define BGROUPS (BATCH / BG)       // 64

#define PREP_BLOCKS 79             // 79*256 = 20224 >= 20000 nodes
#define RT_FIRST    PREP_BLOCKS                  // 79
#define LAMBDA_FIRST (RT_FIRST + BATCH)          // 591
#define LAMBDA_BLOCKS (XTILES * BGROUPS)         // 1280
#define TOTAL_BLOCKS (LAMBDA_FIRST + LAMBDA_BLOCKS)  // 1871

#define CHUNK 20                   // 256*20 >= 5001

#define L2E 1.4426950408889634f
#define LN2 0.6931471805599453f

// Packed f32x2 helpers (Blackwell; ptxas never auto-fuses these)
#define PACK2(out, lo, hi) \
    asm("mov.b64 %0, {%1, %2};" : "=l"(out) : "f"(lo), "f"(hi))
#define UNPACK2(lo, hi, in) \
    asm("mov.b64 {%0, %1}, %2;" : "=f"(lo), "=f"(hi) : "l"(in))
#define FMA2(d, a, b, c) \
    asm("fma.rn.f32x2 %0, %1, %2, %3;" : "=l"(d) : "l"(a), "l"(b), "l"(c))
#define MUL2(d, a, b) \
    asm("mul.rn.f32x2 %0, %1, %2;" : "=l"(d) : "l"(a), "l"(b))

// Scratch (device globals; allocation forbidden)
// d_nodeE[n] = (EV0, EU0, dEV, dEU) where EVe = 2^(L2E * v_n * inv_e)
__device__ float4 d_nodeE[N_NODES];
__device__ int    d_flag;           // prep-done counter, memset to 0 each launch

// stable ps*softplus for the rt path
__device__ __forceinline__ float sp_scaled(float x, float ps, float psln2) {
    float e  = exp2f(-L2E * fabsf(x));
    float lg = __log2f(1.0f + e);
    return fmaf(lg, psln2, ps * fmaxf(x, 0.0f));
}

__device__ __forceinline__ float dot32(const float* __restrict__ a,
                                       const float* __restrict__ w) {
    const float4* a4 = (const float4*)a;
    const float4* w4 = (const float4*)w;
    float s = 0.f;
    #pragma unroll
    for (int q = 0; q < 8; q++) {
        float4 r = __ldg(a4 + q);
        float4 c = __ldg(w4 + q);
        s = fmaf(r.x, c.x, fmaf(r.y, c.y, fmaf(r.z, c.z, fmaf(r.w, c.w, s))));
    }
    return s;
}

// ---------------------------------------------------------------------------
// One kernel, three block roles:
//   [0, 79)      prep: node exp-projections -> d_nodeE, then bump d_flag
//   [79, 591)    rt:   return_time scan for b (no wait on prep)
//   [591, 1871)  lambda: wait for flag, f32x2 path: psln2*log2(1 + E_n*C_b)
// ---------------------------------------------------------------------------
__global__ void __launch_bounds__(256, 6) decoder_kernel(
    float* __restrict__ out,
    const float* __restrict__ emb,
    const int*   __restrict__ assoc,
    const int*   __restrict__ src,
    const int*   __restrict__ pdst,
    const float* __restrict__ last_update,
    const float* __restrict__ cur_time,
    const int*   __restrict__ et,
    const float* __restrict__ W0,
    const float* __restrict__ b0,
    const float* __restrict__ W1,
    const float* __restrict__ b1,
    const float* __restrict__ psi,
    const float* __restrict__ alpha,
    const float* __restrict__ w_t)
{
    int t = threadIdx.x;

    float ps0 = __ldg(psi);
    float ps1 = __ldg(psi + 1);
    float inv0 = 1.0f / (ps0 + 1e-7f);
    float inv1 = 1.0f / (ps1 + 1e-7f);

    if (blockIdx.x < PREP_BLOCKS) {
        // ================= prep: node exp-projections =================
        int node = blockIdx.x * 256 + t;
        if (node < N_NODES) {
            const float4* row = (const float4*)(emb + (size_t)node * EMBED_DIM);
            const float4* w0u = (const float4*)W0;
            const float4* w0v = (const float4*)(W0 + 32);
            const float4* w1u = (const float4*)W1;
            const float4* w1v = (const float4*)(W1 + 32);
            float u0 = 0.f, v0 = 0.f, u1 = 0.f, v1 = 0.f;
            #pragma unroll
            for (int q = 0; q < 8; q++) {
                float4 r  = __ldg(row + q);
                float4 a0 = __ldg(w0u + q), c0 = __ldg(w0v + q);
                float4 a1 = __ldg(w1u + q), c1 = __ldg(w1v + q);
                u0 = fmaf(r.x, a0.x, fmaf(r.y, a0.y, fmaf(r.z, a0.z, fmaf(r.w, a0.w, u0))));
                v0 = fmaf(r.x, c0.x, fmaf(r.y, c0.y, fmaf(r.z, c0.z, fmaf(r.w, c0.w, v0))));
                u1 = fmaf(r.x, a1.x, fmaf(r.y, a1.y, fmaf(r.z, a1.z, fmaf(r.w, a1.w, u1))));
                v1 = fmaf(r.x, c1.x, fmaf(r.y, c1.y, fmaf(r.z, c1.z, fmaf(r.w, c1.w, v1))));
            }
            float EV0 = exp2f(L2E * (v0 * inv0));
            float EU0 = exp2f(L2E * (u0 * inv0));
            float EV1 = exp2f(L2E * (v1 * inv1));
            float EU1 = exp2f(L2E * (u1 * inv1));
            d_nodeE[node] = make_float4(EV0, EU0, EV1 - EV0, EU1 - EU0);
        }
        __threadfence();        // release d_nodeE before flag bump
        __syncthreads();
        if (t == 0) atomicAdd(&d_flag, 1);
        return;
    }

    if (blockIdx.x < LAMBDA_FIRST) {
        // ================= return_time block (one b), stable path =========
        int b = blockIdx.x - RT_FIRST;
        __shared__ float sm_bp[4];   // gbi, ali, wtn, ps

        if (t < 32) {
            int e = (__ldg(et + b) > 0) ? 1 : 0;
            int is = __ldg(assoc + __ldg(src + b));
            int id = __ldg(assoc + __ldg(pdst + b));
            const float* Wu = e ? W1 : W0;
            float sp = __ldg(emb + (size_t)is * EMBED_DIM + t) * __ldg(Wu + t);
            float dp = __ldg(emb + (size_t)id * EMBED_DIM + t) * __ldg(Wu + 32 + t);
            #pragma unroll
            for (int o = 16; o > 0; o >>= 1) {
                sp += __shfl_down_sync(0xffffffffu, sp, o);
                dp += __shfl_down_sync(0xffffffffu, dp, o);
            }
            if (t == 0) {
                float bb = e ? __ldg(b1) : __ldg(b0);
                float inv = e ? inv1 : inv0;
                sm_bp[0] = (sp + dp + bb) * inv;
                sm_bp[1] = __ldg(alpha + e) * inv;
                sm_bp[2] = __ldg(w_t + e) * (L2E / TD_MAX);
                sm_bp[3] = e ? ps1 : ps0;
            }
        }
        __syncthreads();

        float gbi = sm_bp[0], ali = sm_bp[1], wtn = sm_bp[2], ps = sm_bp[3];
        float psln2 = ps * LN2;

        int i0 = t * CHUNK;
        float loc[CHUNK];
        float s = 0.f;
        #pragma unroll
        for (int k = 0; k < CHUNK; k++) {
            int i = i0 + k;
            float inten = 0.f;
            if (i < NUM_SAMPLES) {
                float exc = exp2f(-wtn * (float)i);
                inten = sp_scaled(fmaf(exc, ali, gbi), ps, psln2);
            }
            loc[k] = inten;
            s += inten;
        }

        unsigned m = 0xffffffffu;
        float v = s;
        #pragma unroll
        for (int o = 1; o < 32; o <<= 1) {
            float n = __shfl_up_sync(m, v, o);
            if ((t & 31) >= o) v += n;
        }
        __shared__ float wsum[8];
        if ((t & 31) == 31) wsum[t >> 5] = v;
        __syncthreads();
        if (t < 8) {
            float w = wsum[t];
            #pragma unroll
            for (int o = 1; o < 8; o <<= 1) {
                float n = __shfl_up_sync(0xffu, w, o);
                if (t >= o) w += n;
            }
            wsum[t] = w;
        }
        __syncthreads();
        float excl = (v - s) + ((t >= 32) ? wsum[(t >> 5) - 1] : 0.f);

        float run = excl;
        float acc = 0.f;
        #pragma unroll
        for (int k = 0; k < CHUNK; k++) {
            int i = i0 + k;
            if (i < NUM_SAMPLES) {
                run += loc[k];                          // integral_i (TIMESTEP=1)
                float dens = loc[k] * exp2f(-L2E * run);
                float wgt = (i == NUM_SAMPLES - 1) ? 0.5f : 1.0f;
                acc = fmaf(wgt * (float)i, dens, acc);
            }
        }

        #pragma unroll
        for (int o = 16; o > 0; o >>= 1) acc += __shfl_down_sync(m, acc, o);
        __shared__ float rsum[8];
        if ((t & 31) == 0) rsum[t >> 5] = acc;
        __syncthreads();
        if (t == 0) {
            float tot = 0.f;
            #pragma unroll
            for (int wgrp = 0; wgrp < 8; wgrp++) tot += rsum[wgrp];
            out[(size_t)2 * BATCH * N_NODES + b] = tot;
        }
        return;
    }

    // ================= lambda block: f32x2 + 1-MUFU path =================
    {
        int id   = blockIdx.x - LAMBDA_FIRST;
        int tile = id % XTILES;
        int bg   = id / XTILES;          // [0, 64)
        int x    = tile * 256 + t;       // float4 column

        __shared__ float4 sm_c[BG];      // (CS, CD, e, psln2)

        // batch constants (independent of prep) — overlaps the prep phase
        if (t < BG) {
            int b = bg * BG + t;
            int e = (__ldg(et + b) > 0) ? 1 : 0;
            int is = __ldg(assoc + __ldg(src + b));
            int id2 = __ldg(assoc + __ldg(pdst + b));
            const float* Wu = e ? W1 : W0;
            float bb = e ? __ldg(b1) : __ldg(b0);
            float s = dot32(emb + (size_t)is  * EMBED_DIM, Wu)      + bb;
            float d = dot32(emb + (size_t)id2 * EMBED_DIM, Wu + 32) + bb;
            float al = __ldg(alpha + e), w = __ldg(w_t + e);
            float inv = e ? inv1 : inv0;
            float ps  = e ? ps1 : ps0;
            float ct  = __ldg(cur_time + b);
            float tds = (ct - __ldg(last_update + is))  * (1.0f / TD_MAX);
            float tdd = (ct - __ldg(last_update + id2)) * (1.0f / TD_MAX);
            float cs = (s + al * __expf(-w * tds)) * inv;
            float cd = (d + al * __expf(-w * tdd)) * inv;
            sm_c[t] = make_float4(exp2f(L2E * cs),    // CS = 2^(L2E*cs)
                                  exp2f(L2E * cd),    // CD
                                  (float)e,
                                  ps * LN2);          // psln2
        }

        // wait for prep (projections) to complete
        if (t == 0) {
            while (*(volatile int*)&d_flag < PREP_BLOCKS) __nanosleep(256);
        }
        __syncthreads();
        __threadfence();    // acquire: order subsequent d_nodeE loads

        if (x >= N4) return;

        float4 P0 = d_nodeE[4 * x + 0];   // (EV0, EU0, dEV, dEU)
        float4 P1 = d_nodeE[4 * x + 1];
        float4 P2 = d_nodeE[4 * x + 2];
        float4 P3 = d_nodeE[4 * x + 3];

        // pack node data into b64 pairs once
        uint64_t lo0, hi0, lo1, hi1, lo2, hi2, lo3, hi3, ONE2;
        PACK2(lo0, P0.x, P0.y); PACK2(hi0, P0.z, P0.w);
        PACK2(lo1, P1.x, P1.y); PACK2(hi1, P1.z, P1.w);
        PACK2(lo2, P2.x, P2.y); PACK2(hi2, P2.z, P2.w);
        PACK2(lo3, P3.x, P3.y); PACK2(hi3, P3.z, P3.w);
        PACK2(ONE2, 1.0f, 1.0f);

        float* outs = out + (size_t)(bg * BG) * N_NODES + 4 * x;
        float* outd = outs + (size_t)BATCH * N_NODES;

        #pragma unroll
        for (int bb = 0; bb < BG; bb++) {
            float4 c = sm_c[bb];
            uint64_t efef, cscd, psps;
            PACK2(efef, c.z, c.z);
            PACK2(cscd, c.x, c.y);
            PACK2(psps, c.w, c.w);

            // per node: (EV,EU) = fma2(hi, ef, lo); (aS,aD) = fma2(EV2, CSCD, 1)
            uint64_t ev, a0q, a1q, a2q, a3q;
            FMA2(ev, hi0, efef, lo0); FMA2(a0q, ev, cscd, ONE2);
            FMA2(ev, hi1, efef, lo1); FMA2(a1q, ev, cscd, ONE2);
            FMA2(ev, hi2, efef, lo2); FMA2(a2q, ev, cscd, ONE2);
            FMA2(ev, hi3, efef, lo3); FMA2(a3q, ev, cscd, ONE2);

            float as0, ad0, as1, ad1, as2, ad2, as3, ad3;
            UNPACK2(as0, ad0, a0q);
            UNPACK2(as1, ad1, a1q);
            UNPACK2(as2, ad2, a2q);
            UNPACK2(as3, ad3, a3q);

            float l_s0 = __log2f(as0), l_d0 = __log2f(ad0);
            float l_s1 = __log2f(as1), l_d1 = __log2f(ad1);
            float l_s2 = __log2f(as2), l_d2 = __log2f(ad2);
            float l_s3 = __log2f(as3), l_d3 = __log2f(ad3);

            // scale by psln2 with packed muls, store as 2x b64 each
            uint64_t s01, s23, d01, d23, tmp;
            PACK2(tmp, l_s0, l_s1); MUL2(s01, tmp, psps);
            PACK2(tmp, l_s2, l_s3); MUL2(s23, tmp, psps);
            PACK2(tmp, l_d0, l_d1); MUL2(d01, tmp, psps);
            PACK2(tmp, l_d2, l_d3); MUL2(d23, tmp, psps);

            ulonglong2 vs; vs.x = s01; vs.y = s23;
            ulonglong2 vd; vd.x = d01; vd.y = d23;
            *(ulonglong2*)outs = vs;
            *(ulonglong2*)outd = vd;
            outs += N_NODES;
            outd += N_NODES;
        }
    }
}

// ---------------------------------------------------------------------------
extern "C" void kernel_launch(void* const* d_in, const int* in_sizes, int n_in,
                              void* d_out, int out_size)
{
    (void)in_sizes; (void)n_in; (void)out_size;
    const float* emb   = (const float*)d_in[0];
    const int*   assoc = (const int*)  d_in[1];
    const int*   src   = (const int*)  d_in[2];
    const int*   pdst  = (const int*)  d_in[3];
    const float* lu    = (const float*)d_in[5];
    const float* ct    = (const float*)d_in[6];
    const int*   et    = (const int*)  d_in[7];
    const float* W0    = (const float*)d_in[8];
    const float* b0    = (const float*)d_in[9];
    const float* W1    = (const float*)d_in[10];
    const float* b1    = (const float*)d_in[11];
    const float* psi   = (const float*)d_in[12];
    const float* alpha = (const float*)d_in[13];
    const float* w_t   = (const float*)d_in[14];

    // reset prep-done flag (graph memset node; no alloc, no sync)
    void* flag_ptr = nullptr;
    cudaGetSymbolAddress(&flag_ptr, d_flag);
    cudaMemsetAsync(flag_ptr, 0, sizeof(int));

    decoder_kernel<<<TOTAL_BLOCKS, 256>>>((float*)d_out, emb, assoc, src, pdst,
                                          lu, ct, et, W0, b0, W1, b1,
                                          psi, alpha, w_t);
}

// round 15
// speedup vs baseline: 1.0610x; 1.0610x over previous
#include <cuda_runtime.h>
#include <cuda_bf16.h>
#include <cstdint>

#define N_NODES 20000
#define BATCH 512
#define EMBED_DIM 32
#define NUM_SAMPLES 5001
#define TD_MAX 5000.0f

#define N4 5000                    // float4 columns per row
#define XTILES 20
#define BG 8                       // batch rows per lambda block
#define BGROUPS (BATCH / BG)       // 64

#define PREP_BLOCKS 79             // 79*256 = 20224 >= 20000 nodes
#define RT_FIRST    PREP_BLOCKS                  // 79
#define LAMBDA_FIRST (RT_FIRST + BATCH)          // 591
#define LAMBDA_BLOCKS (XTILES * BGROUPS)         // 1280
#define TOTAL_BLOCKS (LAMBDA_FIRST + LAMBDA_BLOCKS)  // 1871

#define CHUNK 20                   // 256*20 >= 5001

#define L2E 1.4426950408889634f
#define LN2 0.6931471805599453f

// Scratch (device globals; allocation forbidden)
// d_nodeE[n] = (EV0, EU0, dEV, dEU) where EVe = 2^(L2E * v_n * inv_e)
__device__ float4 d_nodeE[N_NODES];
__device__ int    d_flags[PREP_BLOCKS];   // per-prep-block done flags (memset per launch)

// stable ps*softplus for the rt path
__device__ __forceinline__ float sp_scaled(float x, float ps, float psln2) {
    float e  = exp2f(-L2E * fabsf(x));
    float lg = __log2f(1.0f + e);
    return fmaf(lg, psln2, ps * fmaxf(x, 0.0f));
}

__device__ __forceinline__ float dot32(const float* __restrict__ a,
                                       const float* __restrict__ w) {
    const float4* a4 = (const float4*)a;
    const float4* w4 = (const float4*)w;
    float s = 0.f;
    #pragma unroll
    for (int q = 0; q < 8; q++) {
        float4 r = __ldg(a4 + q);
        float4 c = __ldg(w4 + q);
        s = fmaf(r.x, c.x, fmaf(r.y, c.y, fmaf(r.z, c.z, fmaf(r.w, c.w, s))));
    }
    return s;
}

// ---------------------------------------------------------------------------
// One kernel, three block roles:
//   [0, 79)      prep: node exp-projections -> d_nodeE, set d_flags[blockIdx]
//   [79, 591)    rt:   return_time scan for b (never waits)
//   [591, 1871)  lambda: wait only for its 4 prep blocks, then store
// Deadlock-free: prep blocks are the first 79 block ids -> resident in wave 1.
// ---------------------------------------------------------------------------
__global__ void __launch_bounds__(256, 6) decoder_kernel(
    float* __restrict__ out,
    const float* __restrict__ emb,
    const int*   __restrict__ assoc,
    const int*   __restrict__ src,
    const int*   __restrict__ pdst,
    const float* __restrict__ last_update,
    const float* __restrict__ cur_time,
    const int*   __restrict__ et,
    const float* __restrict__ W0,
    const float* __restrict__ b0,
    const float* __restrict__ W1,
    const float* __restrict__ b1,
    const float* __restrict__ psi,
    const float* __restrict__ alpha,
    const float* __restrict__ w_t)
{
    int t = threadIdx.x;

    float ps0 = __ldg(psi);
    float ps1 = __ldg(psi + 1);
    float inv0 = 1.0f / (ps0 + 1e-7f);
    float inv1 = 1.0f / (ps1 + 1e-7f);

    if (blockIdx.x < PREP_BLOCKS) {
        // ================= prep: node exp-projections =================
        int node = blockIdx.x * 256 + t;
        if (node < N_NODES) {
            const float4* row = (const float4*)(emb + (size_t)node * EMBED_DIM);
            const float4* w0u = (const float4*)W0;
            const float4* w0v = (const float4*)(W0 + 32);
            const float4* w1u = (const float4*)W1;
            const float4* w1v = (const float4*)(W1 + 32);
            float u0 = 0.f, v0 = 0.f, u1 = 0.f, v1 = 0.f;
            #pragma unroll
            for (int q = 0; q < 8; q++) {
                float4 r  = __ldg(row + q);
                float4 a0 = __ldg(w0u + q), c0 = __ldg(w0v + q);
                float4 a1 = __ldg(w1u + q), c1 = __ldg(w1v + q);
                u0 = fmaf(r.x, a0.x, fmaf(r.y, a0.y, fmaf(r.z, a0.z, fmaf(r.w, a0.w, u0))));
                v0 = fmaf(r.x, c0.x, fmaf(r.y, c0.y, fmaf(r.z, c0.z, fmaf(r.w, c0.w, v0))));
                u1 = fmaf(r.x, a1.x, fmaf(r.y, a1.y, fmaf(r.z, a1.z, fmaf(r.w, a1.w, u1))));
                v1 = fmaf(r.x, c1.x, fmaf(r.y, c1.y, fmaf(r.z, c1.z, fmaf(r.w, c1.w, v1))));
            }
            float EV0 = exp2f(L2E * (v0 * inv0));
            float EU0 = exp2f(L2E * (u0 * inv0));
            float EV1 = exp2f(L2E * (v1 * inv1));
            float EU1 = exp2f(L2E * (u1 * inv1));
            d_nodeE[node] = make_float4(EV0, EU0, EV1 - EV0, EU1 - EU0);
        }
        __threadfence();        // release d_nodeE before flag set
        __syncthreads();
        if (t == 0) *(volatile int*)&d_flags[blockIdx.x] = 1;
        return;
    }

    if (blockIdx.x < LAMBDA_FIRST) {
        // ================= return_time block (one b), never waits ==========
        int b = blockIdx.x - RT_FIRST;
        __shared__ float sm_bp[4];   // gbi, ali, wtn, ps

        if (t < 32) {
            int e = (__ldg(et + b) > 0) ? 1 : 0;
            int is = __ldg(assoc + __ldg(src + b));
            int id = __ldg(assoc + __ldg(pdst + b));
            const float* Wu = e ? W1 : W0;
            float sp = __ldg(emb + (size_t)is * EMBED_DIM + t) * __ldg(Wu + t);
            float dp = __ldg(emb + (size_t)id * EMBED_DIM + t) * __ldg(Wu + 32 + t);
            #pragma unroll
            for (int o = 16; o > 0; o >>= 1) {
                sp += __shfl_down_sync(0xffffffffu, sp, o);
                dp += __shfl_down_sync(0xffffffffu, dp, o);
            }
            if (t == 0) {
                float bb = e ? __ldg(b1) : __ldg(b0);
                float inv = e ? inv1 : inv0;
                sm_bp[0] = (sp + dp + bb) * inv;
                sm_bp[1] = __ldg(alpha + e) * inv;
                sm_bp[2] = __ldg(w_t + e) * (L2E / TD_MAX);
                sm_bp[3] = e ? ps1 : ps0;
            }
        }
        __syncthreads();

        float gbi = sm_bp[0], ali = sm_bp[1], wtn = sm_bp[2], ps = sm_bp[3];
        float psln2 = ps * LN2;

        int i0 = t * CHUNK;
        float loc[CHUNK];
        float s = 0.f;
        #pragma unroll
        for (int k = 0; k < CHUNK; k++) {
            int i = i0 + k;
            float inten = 0.f;
            if (i < NUM_SAMPLES) {
                float exc = exp2f(-wtn * (float)i);
                inten = sp_scaled(fmaf(exc, ali, gbi), ps, psln2);
            }
            loc[k] = inten;
            s += inten;
        }

        unsigned m = 0xffffffffu;
        float v = s;
        #pragma unroll
        for (int o = 1; o < 32; o <<= 1) {
            float n = __shfl_up_sync(m, v, o);
            if ((t & 31) >= o) v += n;
        }
        __shared__ float wsum[8];
        if ((t & 31) == 31) wsum[t >> 5] = v;
        __syncthreads();
        if (t < 8) {
            float w = wsum[t];
            #pragma unroll
            for (int o = 1; o < 8; o <<= 1) {
                float n = __shfl_up_sync(0xffu, w, o);
                if (t >= o) w += n;
            }
            wsum[t] = w;
        }
        __syncthreads();
        float excl = (v - s) + ((t >= 32) ? wsum[(t >> 5) - 1] : 0.f);

        float run = excl;
        float acc = 0.f;
        #pragma unroll
        for (int k = 0; k < CHUNK; k++) {
            int i = i0 + k;
            if (i < NUM_SAMPLES) {
                run += loc[k];                          // integral_i (TIMESTEP=1)
                float dens = loc[k] * exp2f(-L2E * run);
                float wgt = (i == NUM_SAMPLES - 1) ? 0.5f : 1.0f;
                acc = fmaf(wgt * (float)i, dens, acc);
            }
        }

        #pragma unroll
        for (int o = 16; o > 0; o >>= 1) acc += __shfl_down_sync(m, acc, o);
        __shared__ float rsum[8];
        if ((t & 31) == 0) rsum[t >> 5] = acc;
        __syncthreads();
        if (t == 0) {
            float tot = 0.f;
            #pragma unroll
            for (int wgrp = 0; wgrp < 8; wgrp++) tot += rsum[wgrp];
            out[(size_t)2 * BATCH * N_NODES + b] = tot;
        }
        return;
    }

    // ================= lambda block: scalar 1-MUFU path =================
    {
        int id   = blockIdx.x - LAMBDA_FIRST;
        int tile = id % XTILES;
        int bg   = id / XTILES;          // [0, 64)
        int x    = tile * 256 + t;       // float4 column

        __shared__ float4 sm_c[BG];      // (CS, CD, e, psln2)

        // batch constants (independent of prep) — overlaps the prep phase
        if (t < BG) {
            int b = bg * BG + t;
            int e = (__ldg(et + b) > 0) ? 1 : 0;
            int is = __ldg(assoc + __ldg(src + b));
            int id2 = __ldg(assoc + __ldg(pdst + b));
            const float* Wu = e ? W1 : W0;
            float bb = e ? __ldg(b1) : __ldg(b0);
            float s = dot32(emb + (size_t)is  * EMBED_DIM, Wu)      + bb;
            float d = dot32(emb + (size_t)id2 * EMBED_DIM, Wu + 32) + bb;
            float al = __ldg(alpha + e), w = __ldg(w_t + e);
            float inv = e ? inv1 : inv0;
            float ps  = e ? ps1 : ps0;
            float ct  = __ldg(cur_time + b);
            float tds = (ct - __ldg(last_update + is))  * (1.0f / TD_MAX);
            float tdd = (ct - __ldg(last_update + id2)) * (1.0f / TD_MAX);
            float cs = (s + al * __expf(-w * tds)) * inv;
            float cd = (d + al * __expf(-w * tdd)) * inv;
            sm_c[t] = make_float4(exp2f(L2E * cs),    // CS = 2^(L2E*cs)
                                  exp2f(L2E * cd),    // CD
                                  (float)e,
                                  ps * LN2);          // psln2
        }

        // wait only for the 4 prep blocks covering this tile's 1024 nodes
        if (t == 0) {
            int p0 = 4 * tile;
            int p3 = (p0 + 3 < PREP_BLOCKS) ? p0 + 3 : PREP_BLOCKS - 1;
            volatile int* f = d_flags;
            while (f[p0] + f[p0 + 1] + f[p0 + 2] + f[p3] +
                   ((p0 + 3 < PREP_BLOCKS) ? 0 : f[p3]) < 4 +
                   ((p0 + 3 < PREP_BLOCKS) ? 0 : 0)) {
                // simplified condition below; loop above kept minimal
                if (f[p0] && f[p0 + 1] && f[p0 + 2] && f[p3]) break;
                __nanosleep(128);
            }
        }
        __syncthreads();
        __threadfence();    // acquire: order subsequent d_nodeE loads

        if (x >= N4) return;

        float4 P0 = d_nodeE[4 * x + 0];   // (EV0, EU0, dEV, dEU)
        float4 P1 = d_nodeE[4 * x + 1];
        float4 P2 = d_nodeE[4 * x + 2];
        float4 P3 = d_nodeE[4 * x + 3];

        float* outs = out + (size_t)(bg * BG) * N_NODES + 4 * x;
        float* outd = outs + (size_t)BATCH * N_NODES;

        #pragma unroll
        for (int bb = 0; bb < BG; bb++) {
            float4 c = sm_c[bb];
            float CS = c.x, CD = c.y, ef = c.z, psln2 = c.w;

            float4 ls, ld;
            ls.x = psln2 * __log2f(fmaf(fmaf(ef, P0.z, P0.x), CS, 1.0f));
            ld.x = psln2 * __log2f(fmaf(fmaf(ef, P0.w, P0.y), CD, 1.0f));
            ls.y = psln2 * __log2f(fmaf(fmaf(ef, P1.z, P1.x), CS, 1.0f));
            ld.y = psln2 * __log2f(fmaf(fmaf(ef, P1.w, P1.y), CD, 1.0f));
            ls.z = psln2 * __log2f(fmaf(fmaf(ef, P2.z, P2.x), CS, 1.0f));
            ld.z = psln2 * __log2f(fmaf(fmaf(ef, P2.w, P2.y), CD, 1.0f));
            ls.w = psln2 * __log2f(fmaf(fmaf(ef, P3.z, P3.x), CS, 1.0f));
            ld.w = psln2 * __log2f(fmaf(fmaf(ef, P3.w, P3.y), CD, 1.0f));

            *(float4*)outs = ls;
            *(float4*)outd = ld;
            outs += N_NODES;
            outd += N_NODES;
        }
    }
}

// ---------------------------------------------------------------------------
extern "C" void kernel_launch(void* const* d_in, const int* in_sizes, int n_in,
                              void* d_out, int out_size)
{
    (void)in_sizes; (void)n_in; (void)out_size;
    const float* emb   = (const float*)d_in[0];
    const int*   assoc = (const int*)  d_in[1];
    const int*   src   = (const int*)  d_in[2];
    const int*   pdst  = (const int*)  d_in[3];
    const float* lu    = (const float*)d_in[5];
    const float* ct    = (const float*)d_in[6];
    const int*   et    = (const int*)  d_in[7];
    const float* W0    = (const float*)d_in[8];
    const float* b0    = (const float*)d_in[9];
    const float* W1    = (const float*)d_in[10];
    const float* b1    = (const float*)d_in[11];
    const float* psi   = (const float*)d_in[12];
    const float* alpha = (const float*)d_in[13];
    const float* w_t   = (const float*)d_in[14];

    // reset prep-done flags (graph memset node; no alloc, no sync)
    void* flags_ptr = nullptr;
    cudaGetSymbolAddress(&flags_ptr, d_flags);
    cudaMemsetAsync(flags_ptr, 0, PREP_BLOCKS * sizeof(int));

    decoder_kernel<<<TOTAL_BLOCKS, 256>>>((float*)d_out, emb, assoc, src, pdst,
                                          lu, ct, et, W0, b0, W1, b1,
                                          psi, alpha, w_t);
}